// round 15
// baseline (speedup 1.0000x reference)
#include <cuda_runtime.h>
#include <cuda_bf16.h>
#include <cstdint>

#define BATCH 4096
#define NHID  512
#define BR    32
#define NBKT  1024   // bucket key = lab>>5 ; node2 = 33+bkt, node1 = 1+(bkt>>5)

#define L0_BLOCKS 512          // 4096/8 groups, S=8
#define L1_SLOTS  544          // >= 32 + 4096/8 worst-case level-1 groups (S=8)
#define L2_SLOTS  2048         // >= 1024 + 4096/4 worst-case level-2 groups (S=4)

__device__ int   d_start[NBKT + 1];
__device__ int   d_cur[NBKT];
__device__ int   d_perm[BATCH];
__device__ int   d_g1off[33];        // prefix of level-1 group counts per node
__device__ int   d_g2off[NBKT + 1];  // prefix of level-2 group counts per bucket
__device__ float d_p[3][BATCH];      // per-level probabilities

// ---------------- tables kernel: 256 threads, warp-scan based, few barriers ------------
__global__ __launch_bounds__(256, 1)
void tables_kernel(const int* __restrict__ labels)
{
    __shared__ int hist[NBKT];
    __shared__ int scr[16];          // [0..7] scan1 warp sums, [8..15] scan2 warp sums
    __shared__ int l1cnt[32];

    const int t    = threadIdx.x;    // 0..255
    const int lane = t & 31;
    const int wid  = t >> 5;         // 8 warps

    #pragma unroll
    for (int j = 0; j < 4; j++) hist[j * 256 + t] = 0;
    __syncthreads();
    #pragma unroll
    for (int i = 0; i < 16; i++)
        atomicAdd(&hist[labels[i * 256 + t] >> 5], 1);
    __syncthreads();

    // thread t owns buckets [4t, 4t+4)
    const int h0 = hist[4 * t + 0], h1 = hist[4 * t + 1];
    const int h2 = hist[4 * t + 2], h3 = hist[4 * t + 3];
    const int tot = h0 + h1 + h2 + h3;

    // ---- scan 1: sample-count prefix -> d_start / d_cur ----
    int v = tot;
    #pragma unroll
    for (int o = 1; o < 32; o <<= 1) {
        int u = __shfl_up_sync(0xffffffffu, v, o);
        if (lane >= o) v += u;
    }
    if (lane == 31) scr[wid] = v;

    // ---- scan 2 locals: level-2 group counts ceil(h/4) ----
    const int g0 = (h0 + 3) >> 2, g1 = (h1 + 3) >> 2;
    const int g2 = (h2 + 3) >> 2, g3 = (h3 + 3) >> 2;
    const int gtot = g0 + g1 + g2 + g3;
    int v2 = gtot;
    #pragma unroll
    for (int o = 1; o < 32; o <<= 1) {
        int u = __shfl_up_sync(0xffffffffu, v2, o);
        if (lane >= o) v2 += u;
    }
    if (lane == 31) scr[8 + wid] = v2;

    // ---- level-1 node sums: node n = threads [8n, 8n+8) ----
    int ns = tot;
    ns += __shfl_xor_sync(0xffffffffu, ns, 1);
    ns += __shfl_xor_sync(0xffffffffu, ns, 2);
    ns += __shfl_xor_sync(0xffffffffu, ns, 4);
    if ((t & 7) == 0) l1cnt[t >> 3] = (ns + 7) >> 3;
    __syncthreads();

    // cross-warp scans of the 8 warp sums (both scans at once, warp 0 lanes 0..15)
    if (t < 16) {
        const int slot = t & 7;
        int w = scr[t];
        #pragma unroll
        for (int o = 1; o < 8; o <<= 1) {
            int u = __shfl_up_sync(0x0000ffffu, w, o);
            if (slot >= o) w += u;
        }
        scr[t] = w;
    }
    __syncthreads();

    {
        const int base = (wid > 0 ? scr[wid - 1] : 0) + v - tot;
        int4 st = make_int4(base, base + h0, base + h0 + h1, base + h0 + h1 + h2);
        reinterpret_cast<int4*>(d_start)[t] = st;
        reinterpret_cast<int4*>(d_cur)[t]   = st;
        if (t == 255) d_start[NBKT] = BATCH;
    }
    {
        const int b2 = (wid > 0 ? scr[8 + wid - 1] : 0) + v2 - gtot;
        reinterpret_cast<int4*>(d_g2off)[t] =
            make_int4(b2, b2 + g0, b2 + g0 + g1, b2 + g0 + g1 + g2);
        if (t == 255) d_g2off[NBKT] = b2 + g0 + g1 + g2 + g3;
    }
    if (t == 0) {
        int a = 0;
        d_g1off[0] = 0;
        #pragma unroll
        for (int n = 0; n < 32; n++) { a += l1cnt[n]; d_g1off[n + 1] = a; }
    }
}

// ---------------- scatter kernel: 16 blocks spread the scattered STGs ----------------
__global__ __launch_bounds__(256)
void scatter_kernel(const int* __restrict__ labels)
{
    cudaGridDependencySynchronize();             // wait for tables' d_cur/d_start
    const int i = blockIdx.x * 256 + threadIdx.x;
    const int p = atomicAdd(&d_cur[labels[i] >> 5], 1);
    d_perm[p] = i;
}

// largest k with off[k] <= i
__device__ __forceinline__ int find_bucket(const int* __restrict__ off, int n, int i)
{
    int lo = 0, hi = n;
    while (lo + 1 < hi) {
        int mid = (lo + hi) >> 1;
        if (off[mid] <= i) lo = mid; else hi = mid;
    }
    return lo;
}

// ---- shared prologue: fetch sample ids/steps and stage x -------------------------
template<int SMAX>
__device__ __forceinline__ void stage_samples(
    const float* __restrict__ x, const int* __restrict__ labels,
    float4* __restrict__ xsv, int* __restrict__ sid_sm, int* __restrict__ step_sm,
    int shift, int base, int S, bool use_perm)
{
    const int tid = threadIdx.x;
    if (tid < S) {
        const int sb = use_perm ? d_perm[base + tid] : (base + tid);
        sid_sm[tid]  = sb;
        step_sm[tid] = (labels[sb] >> shift) & 31;
    }
    __syncthreads();
    #pragma unroll
    for (int s = 0; s < SMAX; s++) {
        if (s < S) {
            const float4* xg = reinterpret_cast<const float4*>(x + (size_t)sid_sm[s] * NHID);
            xsv[s * 128 + tid] = xg[tid];
        }
    }
    __syncthreads();
}

// ---------------- FMA2 group task: SMAX samples x one node, 4-warp h-split ------------
template<int SMAX, int LVL>
__device__ __forceinline__ void process_group_fma2(
    const float* __restrict__ x, const int* __restrict__ labels,
    const float* __restrict__ W,
    float4* __restrict__ xsv, float* __restrict__ part,
    int* __restrict__ sid_sm, int* __restrict__ step_sm,
    int node, int shift, int base, int S, bool use_perm)
{
    const int tid  = threadIdx.x;
    const int warp = tid >> 5;
    const int lane = tid & 31;

    stage_samples<SMAX>(x, labels, xsv, sid_sm, step_sm, shift, base, S, use_perm);

    const float* __restrict__ Wq =
        W + (size_t)node * (NHID * BR) + (warp * 128) * BR + lane;

    const uint32_t xbase =
        (uint32_t)__cvta_generic_to_shared(xsv) + (warp * 32) * 16;

    uint64_t acc2[SMAX];
    #pragma unroll
    for (int s = 0; s < SMAX; s++) acc2[s] = 0ull;

    #pragma unroll 8
    for (int t = 0; t < 32; t++) {
        const float w0 = __ldg(Wq + (4 * t + 0) * BR);
        const float w1 = __ldg(Wq + (4 * t + 1) * BR);
        const float w2 = __ldg(Wq + (4 * t + 2) * BR);
        const float w3 = __ldg(Wq + (4 * t + 3) * BR);
        uint64_t w01, w23;
        asm("mov.b64 %0, {%1, %2};" : "=l"(w01) : "f"(w0), "f"(w1));
        asm("mov.b64 %0, {%1, %2};" : "=l"(w23) : "f"(w2), "f"(w3));
        #pragma unroll
        for (int s = 0; s < SMAX; s++) {
            uint64_t x01, x23;
            const uint32_t a = xbase + (s * 128 + t) * 16;
            asm volatile("ld.shared.v2.u64 {%0, %1}, [%2];"
                         : "=l"(x01), "=l"(x23) : "r"(a));
            asm("fma.rn.f32x2 %0, %1, %2, %0;" : "+l"(acc2[s]) : "l"(x01), "l"(w01));
            asm("fma.rn.f32x2 %0, %1, %2, %0;" : "+l"(acc2[s]) : "l"(x23), "l"(w23));
        }
    }

    #pragma unroll
    for (int s = 0; s < SMAX; s++) {
        float lo, hi;
        asm("mov.b64 {%0, %1}, %2;" : "=f"(lo), "=f"(hi) : "l"(acc2[s]));
        part[(warp * SMAX + s) * 32 + lane] = lo + hi;
    }
    __syncthreads();

    #pragma unroll
    for (int si = warp; si < SMAX; si += 4) {
        float logit = part[(0 * SMAX + si) * 32 + lane]
                    + part[(1 * SMAX + si) * 32 + lane]
                    + part[(2 * SMAX + si) * 32 + lane]
                    + part[(3 * SMAX + si) * 32 + lane];
        float m = logit;
        #pragma unroll
        for (int o = 16; o; o >>= 1) m = fmaxf(m, __shfl_xor_sync(0xffffffffu, m, o));
        const float e = __expf(logit - m);
        float ssum = e;
        #pragma unroll
        for (int o = 16; o; o >>= 1) ssum += __shfl_xor_sync(0xffffffffu, ssum, o);
        if (si < S) {
            const float es = __shfl_sync(0xffffffffu, e, step_sm[si]);
            if (lane == 0) d_p[LVL][sid_sm[si]] = es / ssum;
        }
    }
}

// ---------------- unified levels kernel: level-0 blocks skip the dependency sync ------
__global__ __launch_bounds__(128)
void levels_kernel(const float* __restrict__ x,
                   const int* __restrict__ labels,
                   const float* __restrict__ W)
{
    __shared__ float4 xsv[8 * 128];        // 16 KB
    __shared__ float  part[4 * 8 * 32];    // 4 KB
    __shared__ int    sid_sm[8];
    __shared__ int    step_sm[8];

    const int blk = blockIdx.x;

    if (blk < L0_BLOCKS) {
        // Sort-independent: runs concurrently with tables+scatter (no grid sync).
        process_group_fma2<8, 0>(x, labels, W, xsv, part, sid_sm, step_sm,
                                 /*node=*/0, /*shift=*/10, blk * 8, 8, false);
    } else if (blk < L0_BLOCKS + L1_SLOTS) {
        cudaGridDependencySynchronize();         // needs d_perm / task tables
        const int i = blk - L0_BLOCKS;
        if (i >= d_g1off[32]) return;
        const int g    = find_bucket(d_g1off, 32, i);
        const int base = d_start[g * 32] + (i - d_g1off[g]) * 8;
        const int S    = min(8, d_start[g * 32 + 32] - base);
        process_group_fma2<8, 1>(x, labels, W, xsv, part, sid_sm, step_sm,
                                 1 + g, /*shift=*/5, base, S, true);
    } else {
        cudaGridDependencySynchronize();         // needs d_perm / task tables
        const int i = blk - (L0_BLOCKS + L1_SLOTS);
        if (i >= d_g2off[NBKT]) return;
        const int k    = find_bucket(d_g2off, NBKT, i);
        const int base = d_start[k] + (i - d_g2off[k]) * 4;
        const int S    = min(4, d_start[k + 1] - base);
        process_group_fma2<4, 2>(x, labels, W, xsv, part, sid_sm, step_sm,
                                 33 + k, /*shift=*/0, base, S, true);
    }
}

__global__ __launch_bounds__(256)
void combine_kernel(float* __restrict__ out)
{
    cudaGridDependencySynchronize();             // wait for all d_p writes
    const int b = blockIdx.x * 256 + threadIdx.x;
    out[b] = d_p[0][b] * d_p[1][b] * d_p[2][b];
}

// ---------------- launch with PDL chaining ----------------
template<typename... Args>
static void launch_pdl(void (*kern)(Args...), dim3 grid, dim3 block, Args... args)
{
    cudaLaunchConfig_t cfg = {};
    cfg.gridDim  = grid;
    cfg.blockDim = block;
    cfg.stream   = 0;
    cudaLaunchAttribute attr[1];
    attr[0].id = cudaLaunchAttributeProgrammaticStreamSerialization;
    attr[0].val.programmaticStreamSerializationAllowed = 1;
    cfg.attrs    = attr;
    cfg.numAttrs = 1;
    cudaLaunchKernelEx(&cfg, kern, args...);
}

extern "C" void kernel_launch(void* const* d_in, const int* in_sizes, int n_in,
                              void* d_out, int out_size)
{
    const float* x      = (const float*)d_in[0];   // [4096, 512] f32
    const int*   labels = (const int*)d_in[1];     // [4096] i32
    const float* W      = (const float*)d_in[2];   // [1057, 512, 32] f32
    float*       out    = (float*)d_out;           // [4096] f32

    tables_kernel<<<1, 256>>>(labels);
    launch_pdl(scatter_kernel, dim3(16), dim3(256), labels);
    launch_pdl(levels_kernel, dim3(L0_BLOCKS + L1_SLOTS + L2_SLOTS), dim3(128), x, labels, W);
    launch_pdl(combine_kernel, dim3(BATCH / 256), dim3(256), out);
}